// round 16
// baseline (speedup 1.0000x reference)
#include <cuda_runtime.h>
#include <cuda_bf16.h>
#include <math.h>

// Problem constants
constexpr int B_  = 2;
constexpr int C_  = 768;
constexpr int N_  = 2744;          // 14^3 tokens
constexpr int NH  = 12;
constexpr int DH  = 64;
constexpr int M_  = B_ * N_;       // 5488 total tokens

// Q pre-scale folded into qkv epilogue: 0.125 * log2(e)
constexpr float QSCALE = 0.18033688f;

// Scratch (device globals; no allocation allowed)
__device__ __nv_bfloat16 g_tn  [M_ * C_];
__device__ __nv_bfloat16 g_ao  [M_ * C_];
__device__ __nv_bfloat16 g_wqkv[3 * C_ * C_];
__device__ __nv_bfloat16 g_wout[C_ * C_];
__device__ __nv_bfloat16 g_q [B_ * NH * N_ * DH];
__device__ __nv_bfloat16 g_k [B_ * NH * N_ * DH];
__device__ __nv_bfloat16 g_v [B_ * NH * N_ * DH];

// ---------------------------------------------------------------------------
// Helpers
// ---------------------------------------------------------------------------
__device__ __forceinline__ unsigned pack_bf16(float lo, float hi) {
    unsigned r;
    asm("cvt.rn.bf16x2.f32 %0, %1, %2;" : "=r"(r) : "f"(hi), "f"(lo));
    return r;
}
__device__ __forceinline__ float ex2f(float x) {
    float y;
    asm("ex2.approx.f32 %0, %1;" : "=f"(y) : "f"(x));
    return y;
}

__device__ __forceinline__ void mma16816(float* d, const unsigned* a,
                                         unsigned b0, unsigned b1) {
    asm volatile(
        "mma.sync.aligned.m16n8k16.row.col.f32.bf16.bf16.f32 "
        "{%0,%1,%2,%3}, {%4,%5,%6,%7}, {%8,%9}, {%0,%1,%2,%3};"
        : "+f"(d[0]), "+f"(d[1]), "+f"(d[2]), "+f"(d[3])
        : "r"(a[0]), "r"(a[1]), "r"(a[2]), "r"(a[3]), "r"(b0), "r"(b1));
}

__device__ __forceinline__ void ldsm_x4(unsigned* r, unsigned addr) {
    asm volatile("ldmatrix.sync.aligned.m8n8.x4.shared.b16 {%0,%1,%2,%3}, [%4];"
                 : "=r"(r[0]), "=r"(r[1]), "=r"(r[2]), "=r"(r[3]) : "r"(addr));
}
__device__ __forceinline__ void ldsm_x4_t(unsigned* r, unsigned addr) {
    asm volatile("ldmatrix.sync.aligned.m8n8.x4.trans.shared.b16 {%0,%1,%2,%3}, [%4];"
                 : "=r"(r[0]), "=r"(r[1]), "=r"(r[2]), "=r"(r[3]) : "r"(addr));
}

__device__ __forceinline__ void cp16(unsigned dst, const void* src, bool pred) {
    unsigned sz = pred ? 16u : 0u;
    asm volatile("cp.async.cg.shared.global [%0], [%1], 16, %2;"
                 :: "r"(dst), "l"(src), "r"(sz));
}
__device__ __forceinline__ void cp_commit() {
    asm volatile("cp.async.commit_group;" ::: "memory");
}
__device__ __forceinline__ void cp_wait1() {
    asm volatile("cp.async.wait_group 1;" ::: "memory");
}
__device__ __forceinline__ void cp_wait0() {
    asm volatile("cp.async.wait_group 0;" ::: "memory");
}

// Lane address for a 16x16 bf16 block at (row0, halfcol0); row stride 144B.
__device__ __forceinline__ unsigned frag_addr(unsigned base, int row0,
                                              int halfcol0, int lane) {
    int lrow = lane & 7, lm = lane >> 3;
    return base + (unsigned)((row0 + (lm & 1) * 8 + lrow) * 144 +
                             halfcol0 * 2 + (lm >> 1) * 16);
}

// ---------------------------------------------------------------------------
// Kernel 0: fp32 -> bf16 conversion of both weight matrices in one launch.
// ---------------------------------------------------------------------------
constexpr int CVT_NQ = 3 * C_ * C_ / 2;
constexpr int CVT_NO = C_ * C_ / 2;
__global__ void cvt_kernel(const float* __restrict__ qkvw,
                           const float* __restrict__ outw) {
    int i = blockIdx.x * blockDim.x + threadIdx.x;
    if (i < CVT_NQ) {
        float2 v = *(const float2*)(qkvw + (size_t)i * 2);
        ((unsigned*)g_wqkv)[i] = pack_bf16(v.x, v.y);
    } else if (i < CVT_NQ + CVT_NO) {
        int j = i - CVT_NQ;
        float2 v = *(const float2*)(outw + (size_t)j * 2);
        ((unsigned*)g_wout)[j] = pack_bf16(v.x, v.y);
    }
}

// ---------------------------------------------------------------------------
// Kernel 1: LayerNorm, coalesced two-pass.
// ---------------------------------------------------------------------------
__global__ void __launch_bounds__(256) ln_kernel(
        const float* __restrict__ x,
        const float* __restrict__ w,
        const float* __restrict__ bnorm) {
    __shared__ float s1s[8][32], s2s[8][32];
    __shared__ float smu[32], sinv[32];
    __shared__ float tile[32][66];

    int tid = threadIdx.x, wrp = tid >> 5, lane = tid & 31;
    int m  = blockIdx.x * 32 + lane;
    int mc = m < M_ ? m : M_ - 1;
    int b = mc / N_, n = mc % N_;
    const float* xb = x + (size_t)b * C_ * N_ + n;

    float s1 = 0.f, s2 = 0.f;
    for (int c = wrp; c < C_; c += 8) {
        float v = xb[(size_t)c * N_];
        s1 += v; s2 += v * v;
    }
    s1s[wrp][lane] = s1; s2s[wrp][lane] = s2;
    __syncthreads();
    if (wrp == 0) {
        float a = 0.f, q = 0.f;
        #pragma unroll
        for (int i = 0; i < 8; ++i) { a += s1s[i][lane]; q += s2s[i][lane]; }
        float mu = a * (1.f / C_);
        float var = q * (1.f / C_) - mu * mu;
        smu[lane] = mu;
        sinv[lane] = rsqrtf(var + 1e-5f);
    }
    __syncthreads();
    float mu = smu[lane], inv = sinv[lane];

    for (int ch = 0; ch < C_ / 64; ++ch) {
        #pragma unroll
        for (int j = 0; j < 8; ++j) {
            int cl = wrp + 8 * j;
            int c = ch * 64 + cl;
            float v = xb[(size_t)c * N_];
            tile[lane][cl] = (v - mu) * inv * w[c] + bnorm[c];
        }
        __syncthreads();
        #pragma unroll
        for (int r = 0; r < 4; ++r) {
            int idx = tid + r * 256;
            int tok = idx >> 5, chalf = idx & 31;
            int mm = blockIdx.x * 32 + tok;
            if (mm < M_) {
                float lo = tile[tok][chalf * 2];
                float hi = tile[tok][chalf * 2 + 1];
                ((unsigned*)g_tn)[((size_t)mm * C_ + ch * 64) / 2 + chalf] =
                    pack_bf16(lo, hi);
            }
        }
        __syncthreads();
    }
}

// ---------------------------------------------------------------------------
// Kernel 2: QKV GEMM, 128x128 tile, cp.async double-buffered.
// Q output pre-scaled by QSCALE.
// ---------------------------------------------------------------------------
constexpr unsigned QKV_BUF = 36864u;
constexpr unsigned QKV_SMEM = 2 * QKV_BUF;

__global__ void __launch_bounds__(256) qkv_mma_kernel() {
    extern __shared__ __align__(16) char dsm[];
    unsigned smb = (unsigned)__cvta_generic_to_shared(dsm);

    int m0 = blockIdx.y * 128;
    int j0 = blockIdx.x * 128;
    int tid = threadIdx.x;
    int w = tid >> 5, lane = tid & 31;
    int wm = (w & 3) * 32;
    int wn = (w >> 2) * 64;
    int gr = lane >> 2, qd = lane & 3;

    auto stage = [&](int buf, int k0) {
        unsigned ab = smb + buf * QKV_BUF;
        unsigned bb = ab + 18432u;
        #pragma unroll
        for (int r = 0; r < 4; ++r) {
            int idx = tid + r * 256;
            int row = idx >> 3, seg = idx & 7;
            int m = m0 + row;
            cp16(ab + row * 144 + seg * 16,
                 g_tn + (size_t)m * C_ + k0 + seg * 8, m < M_);
            cp16(bb + row * 144 + seg * 16,
                 g_wqkv + (size_t)(j0 + row) * C_ + k0 + seg * 8, true);
        }
        cp_commit();
    };

    float of[2][8][4] = {};
    constexpr int NC = C_ / 64;

    stage(0, 0);
    for (int kc = 0; kc < NC; ++kc) {
        if (kc + 1 < NC) { stage((kc + 1) & 1, (kc + 1) * 64); cp_wait1(); }
        else             { cp_wait0(); }
        __syncthreads();

        unsigned ab = smb + (kc & 1) * QKV_BUF;
        unsigned bb = ab + 18432u;
        #pragma unroll
        for (int ks = 0; ks < 4; ++ks) {
            unsigned a0[4], a1[4];
            ldsm_x4(a0, frag_addr(ab, wm,      ks * 16, lane));
            ldsm_x4(a1, frag_addr(ab, wm + 16, ks * 16, lane));
            #pragma unroll
            for (int nt = 0; nt < 4; ++nt) {
                unsigned b[4];
                ldsm_x4(b, frag_addr(bb, wn + nt * 16, ks * 16, lane));
                mma16816(of[0][nt * 2    ], a0, b[0], b[2]);
                mma16816(of[0][nt * 2 + 1], a0, b[1], b[3]);
                mma16816(of[1][nt * 2    ], a1, b[0], b[2]);
                mma16816(of[1][nt * 2 + 1], a1, b[1], b[3]);
            }
        }
        __syncthreads();
    }

    int js = j0 + wn;
    int s = js / C_;
    int h = (js % C_) / DH;
    __nv_bfloat16* outp = (s == 0) ? g_q : ((s == 1) ? g_k : g_v);
    float sc = (s == 0) ? QSCALE : 1.0f;
    unsigned* o32 = (unsigned*)outp;
    #pragma unroll
    for (int mt = 0; mt < 2; ++mt) {
        int ma = m0 + wm + mt * 16 + gr;
        int mb2 = ma + 8;
        #pragma unroll
        for (int j = 0; j < 8; ++j) {
            int e = j * 8 + qd * 2;
            if (ma < M_) {
                int b = ma / N_, n = ma % N_;
                o32[((size_t)((b * NH + h) * N_ + n) * DH + e) >> 1] =
                    pack_bf16(of[mt][j][0] * sc, of[mt][j][1] * sc);
            }
            if (mb2 < M_) {
                int b = mb2 / N_, n = mb2 % N_;
                o32[((size_t)((b * NH + h) * N_ + n) * DH + e) >> 1] =
                    pack_bf16(of[mt][j][2] * sc, of[mt][j][3] * sc);
            }
        }
    }
}

// ---------------------------------------------------------------------------
// Kernel 3: attention, 64-query blocks (128 threads, 4 warps) for wave
// efficiency: grid 24x43=1032 CTAs at 4 CTAs/SM (smem 46080B) = 1.74 waves
// vs 1.19 before. Double-buffered K/V (trailing barrier per tile makes it
// safe, same protocol as qkv). Per-warp compute identical to round 15.
// smem: Qs @0 (9216) + 2 x (K 9216 | V 9216) = 46080B.
// ---------------------------------------------------------------------------
constexpr unsigned ATT_RING = 9216u;
constexpr unsigned ATT_STAGE = 18432u;
constexpr unsigned ATT_SMEM = 9216u + 2 * ATT_STAGE;   // 46080

__global__ void __launch_bounds__(128, 4) attn_mma_kernel() {
    extern __shared__ __align__(16) char dsm[];
    unsigned smb = (unsigned)__cvta_generic_to_shared(dsm);

    int bh = blockIdx.x;
    int q0 = blockIdx.y * 64;
    const __nv_bfloat16* qb = g_q + (size_t)bh * N_ * DH;
    const __nv_bfloat16* kb = g_k + (size_t)bh * N_ * DH;
    const __nv_bfloat16* vb = g_v + (size_t)bh * N_ * DH;

    int tid  = threadIdx.x;
    int w    = tid >> 5, lane = tid & 31;
    int wq   = w * 16;                 // 4 warps x 16 queries = 64
    int gr   = lane >> 2;
    int qd   = lane & 3;
    int row2 = tid >> 1, h2 = tid & 1; // staging: 128 thr = 64 rows x 2 halves

    auto stage = [&](int buf, int kb0) {
        int n = kb0 + row2;
        bool ok = n < N_;
        unsigned base = smb + ATT_RING + buf * ATT_STAGE;
        unsigned kdst = base + row2 * 144 + h2 * 64;
        unsigned vdst = base + 9216u + row2 * 144 + h2 * 64;
        const char* ksrc = (const char*)(kb + (size_t)n * DH + h2 * 32);
        const char* vsrc = (const char*)(vb + (size_t)n * DH + h2 * 32);
        #pragma unroll
        for (int c = 0; c < 4; ++c) {
            cp16(kdst + c * 16, ksrc + c * 16, ok);
            cp16(vdst + c * 16, vsrc + c * 16, ok);
        }
        cp_commit();
    };

    {   // stage Q tile: 64 rows x 64 bf16 (512 segs / 128 thr = 4 each)
        #pragma unroll
        for (int r = 0; r < 4; ++r) {
            int idx = tid + r * 128;
            int row = idx >> 3, seg = idx & 7;
            int n = q0 + row;
            uint4 v = make_uint4(0u,0u,0u,0u);
            if (n < N_)
                v = *(const uint4*)(qb + (size_t)n * DH + seg * 8);
            *(uint4*)((unsigned*)dsm + row * 36 + seg * 4) = v;
        }
    }

    constexpr int NT = (N_ + 63) / 64;
    stage(0, 0);
    __syncthreads();

    unsigned qa[4][4];
    #pragma unroll
    for (int ks = 0; ks < 4; ++ks)
        ldsm_x4(qa[ks], frag_addr(smb, wq, ks * 16, lane));

    float of[8][4] = {};
    float lp0 = 0.f, lp1 = 0.f;

    for (int kc = 0; kc < NT; ++kc) {
        int kb0 = kc * 64;
        if (kc + 1 < NT) { stage((kc + 1) & 1, kb0 + 64); cp_wait1(); }
        else             { cp_wait0(); }
        __syncthreads();                     // buffer kc&1 visible

        unsigned ksb = smb + ATT_RING + (kc & 1) * ATT_STAGE;
        unsigned vsb = ksb + 9216u;
        bool full = (kb0 + 64 <= N_);

        #pragma unroll
        for (int p = 0; p < 4; ++p) {        // 16-key group
            float s0[4] = {}, s1[4] = {};
            #pragma unroll
            for (int ks = 0; ks < 4; ++ks) {
                unsigned bb[4];
                ldsm_x4(bb, frag_addr(ksb, p * 16, ks * 16, lane));
                mma16816(s0, qa[ks], bb[0], bb[2]);
                mma16816(s1, qa[ks], bb[1], bb[3]);
            }

            unsigned a[4];
            if (full) {
                float p0 = ex2f(s0[0]), p1 = ex2f(s0[1]);
                float p2 = ex2f(s0[2]), p3 = ex2f(s0[3]);
                float p4 = ex2f(s1[0]), p5 = ex2f(s1[1]);
                float p6 = ex2f(s1[2]), p7 = ex2f(s1[3]);
                lp0 += (p0 + p1) + (p4 + p5);
                lp1 += (p2 + p3) + (p6 + p7);
                a[0] = pack_bf16(p0, p1); a[1] = pack_bf16(p2, p3);
                a[2] = pack_bf16(p4, p5); a[3] = pack_bf16(p6, p7);
            } else {
                int gk0 = kb0 + p * 16 + qd * 2;
                int gk1 = gk0 + 8;
                bool u0 = gk0 < N_, u1 = (gk0 + 1) < N_;
                bool u2 = gk1 < N_, u3 = (gk1 + 1) < N_;
                float p0 = u0 ? ex2f(s0[0]) : 0.f;
                float p1 = u1 ? ex2f(s0[1]) : 0.f;
                float p2 = u0 ? ex2f(s0[2]) : 0.f;
                float p3 = u1 ? ex2f(s0[3]) : 0.f;
                float p4 = u2 ? ex2f(s1[0]) : 0.f;
                float p5 = u3 ? ex2f(s1[1]) : 0.f;
                float p6 = u2 ? ex2f(s1[2]) : 0.f;
                float p7 = u3 ? ex2f(s1[3]) : 0.f;
                lp0 += (p0 + p1) + (p4 + p5);
                lp1 += (p2 + p3) + (p6 + p7);
                a[0] = pack_bf16(p0, p1); a[1] = pack_bf16(p2, p3);
                a[2] = pack_bf16(p4, p5); a[3] = pack_bf16(p6, p7);
            }

            #pragma unroll
            for (int g = 0; g < 4; ++g) {
                unsigned v[4];
                ldsm_x4_t(v, frag_addr(vsb, p * 16, g * 16, lane));
                mma16816(of[2 * g    ], a, v[0], v[1]);
                mma16816(of[2 * g + 1], a, v[2], v[3]);
            }
        }
        __syncthreads();                     // reads done; buffer reusable
    }

    lp0 += __shfl_xor_sync(0xffffffffu, lp0, 1);
    lp0 += __shfl_xor_sync(0xffffffffu, lp0, 2);
    lp1 += __shfl_xor_sync(0xffffffffu, lp1, 1);
    lp1 += __shfl_xor_sync(0xffffffffu, lp1, 2);
    float invl0 = 1.f / lp0;
    float invl1 = 1.f / lp1;

    int b = bh / NH, h = bh % NH;
    int n0 = q0 + wq + gr;
    int n1 = n0 + 8;
    unsigned* ao32 = reinterpret_cast<unsigned*>(g_ao);
    #pragma unroll
    for (int t = 0; t < 8; ++t) {
        int e = t * 8 + qd * 2;
        if (n0 < N_)
            ao32[((size_t)(b * N_ + n0) * C_ + h * DH + e) >> 1] =
                pack_bf16(of[t][0] * invl0, of[t][1] * invl0);
        if (n1 < N_)
            ao32[((size_t)(b * N_ + n1) * C_ + h * DH + e) >> 1] =
                pack_bf16(of[t][2] * invl1, of[t][3] * invl1);
    }
}

// ---------------------------------------------------------------------------
// Kernel 4: out projection, 128x64 tile, cp.async double-buffered.
// ---------------------------------------------------------------------------
constexpr unsigned PROJ_BUF  = 27648u;
constexpr unsigned PROJ_SMEM = 2 * PROJ_BUF;

__global__ void __launch_bounds__(256) proj_mma_kernel(
        const float* __restrict__ bout,
        const float* __restrict__ x,
        float* __restrict__ out) {
    extern __shared__ __align__(16) char dsm[];
    unsigned smb = (unsigned)__cvta_generic_to_shared(dsm);
    float* Ts = (float*)dsm;

    int m0 = blockIdx.y * 128;
    int c0 = blockIdx.x * 64;
    int tid = threadIdx.x;
    int w = tid >> 5, lane = tid & 31;
    int wm = (w & 3) * 32;
    int wn = (w >> 2) * 32;
    int gr = lane >> 2, qd = lane & 3;

    auto stage = [&](int buf, int k0) {
        unsigned ab = smb + buf * PROJ_BUF;
        unsigned bb = ab + 18432u;
        #pragma unroll
        for (int r = 0; r < 4; ++r) {
            int idx = tid + r * 256;
            int row = idx >> 3, seg = idx & 7;
            int m = m0 + row;
            cp16(ab + row * 144 + seg * 16,
                 g_ao + (size_t)m * C_ + k0 + seg * 8, m < M_);
        }
        #pragma unroll
        for (int r = 0; r < 2; ++r) {
            int idx = tid + r * 256;
            int row = idx >> 3, seg = idx & 7;
            cp16(bb + row * 144 + seg * 16,
                 g_wout + (size_t)(c0 + row) * C_ + k0 + seg * 8, true);
        }
        cp_commit();
    };

    float of[2][4][4] = {};
    constexpr int NC = C_ / 64;

    stage(0, 0);
    for (int kc = 0; kc < NC; ++kc) {
        if (kc + 1 < NC) { stage((kc + 1) & 1, (kc + 1) * 64); cp_wait1(); }
        else             { cp_wait0(); }
        __syncthreads();

        unsigned ab = smb + (kc & 1) * PROJ_BUF;
        unsigned bb = ab + 18432u;
        #pragma unroll
        for (int ks = 0; ks < 4; ++ks) {
            unsigned a0[4], a1[4];
            ldsm_x4(a0, frag_addr(ab, wm,      ks * 16, lane));
            ldsm_x4(a1, frag_addr(ab, wm + 16, ks * 16, lane));
            #pragma unroll
            for (int nt = 0; nt < 2; ++nt) {
                unsigned b[4];
                ldsm_x4(b, frag_addr(bb, wn + nt * 16, ks * 16, lane));
                mma16816(of[0][nt * 2    ], a0, b[0], b[2]);
                mma16816(of[0][nt * 2 + 1], a0, b[1], b[3]);
                mma16816(of[1][nt * 2    ], a1, b[0], b[2]);
                mma16816(of[1][nt * 2 + 1], a1, b[1], b[3]);
            }
        }
        __syncthreads();
    }

    #pragma unroll
    for (int mt = 0; mt < 2; ++mt) {
        #pragma unroll
        for (int j = 0; j < 4; ++j) {
            int cl = wn + j * 8 + qd * 2;
            float b0 = bout[c0 + cl], b1 = bout[c0 + cl + 1];
            int r0 = wm + mt * 16 + gr;
            Ts[r0 * 65 + cl]           = of[mt][j][0] + b0;
            Ts[r0 * 65 + cl + 1]       = of[mt][j][1] + b1;
            Ts[(r0 + 8) * 65 + cl]     = of[mt][j][2] + b0;
            Ts[(r0 + 8) * 65 + cl + 1] = of[mt][j][3] + b1;
        }
    }
    __syncthreads();

    for (int t = tid; t < 128 * 64; t += 256) {
        int cl = t >> 7, ml = t & 127;
        int m = m0 + ml;
        if (m < M_) {
            int b = m / N_, n = m % N_;
            size_t gi = (size_t)(b * C_ + c0 + cl) * N_ + n;
            out[gi] = Ts[ml * 65 + cl] + x[gi];
        }
    }
}

// ---------------------------------------------------------------------------
extern "C" void kernel_launch(void* const* d_in, const int* in_sizes, int n_in,
                              void* d_out, int out_size) {
    const float* x      = nullptr;
    const float* norm_w = nullptr;
    const float* norm_b = nullptr;
    const float* qkv_w  = nullptr;
    const float* out_w  = nullptr;
    const float* out_b  = nullptr;
    int small_seen = 0;
    for (int i = 0; i < n_in; ++i) {
        const float* p = (const float*)d_in[i];
        int sz = in_sizes[i];
        if      (sz == B_ * C_ * N_)     x     = p;
        else if (sz == 3 * C_ * C_)      qkv_w = p;
        else if (sz == C_ * C_)          out_w = p;
        else if (sz == C_) {
            if      (small_seen == 0) norm_w = p;
            else if (small_seen == 1) norm_b = p;
            else                      out_b  = p;
            ++small_seen;
        }
    }
    float* out = (float*)d_out;
    (void)out_size;

    // Idempotent, host-side, capture-safe.
    cudaFuncSetAttribute(qkv_mma_kernel,
                         cudaFuncAttributeMaxDynamicSharedMemorySize, QKV_SMEM);
    cudaFuncSetAttribute(attn_mma_kernel,
                         cudaFuncAttributeMaxDynamicSharedMemorySize, ATT_SMEM);
    cudaFuncSetAttribute(proj_mma_kernel,
                         cudaFuncAttributeMaxDynamicSharedMemorySize, PROJ_SMEM);

    cvt_kernel<<<(CVT_NQ + CVT_NO + 255) / 256, 256>>>(qkv_w, out_w);
    ln_kernel<<<(M_ + 31) / 32, 256>>>(x, norm_w, norm_b);
    qkv_mma_kernel<<<dim3(3 * C_ / 128, (M_ + 127) / 128), 256, QKV_SMEM>>>();
    attn_mma_kernel<<<dim3(B_ * NH, (N_ + 63) / 64), 128, ATT_SMEM>>>();
    proj_mma_kernel<<<dim3(C_ / 64, (M_ + 127) / 128), 256, PROJ_SMEM>>>(out_b, x, out);
}

// round 17
// speedup vs baseline: 1.0420x; 1.0420x over previous
#include <cuda_runtime.h>
#include <cuda_bf16.h>
#include <math.h>

// Problem constants
constexpr int B_  = 2;
constexpr int C_  = 768;
constexpr int N_  = 2744;          // 14^3 tokens
constexpr int NH  = 12;
constexpr int DH  = 64;
constexpr int M_  = B_ * N_;       // 5488 total tokens

// Q pre-scale folded into qkv epilogue: 0.125 * log2(e)
constexpr float QSCALE = 0.18033688f;

// Scratch (device globals; no allocation allowed)
__device__ __nv_bfloat16 g_tn  [M_ * C_];
__device__ __nv_bfloat16 g_ao  [M_ * C_];
__device__ __nv_bfloat16 g_wqkv[3 * C_ * C_];
__device__ __nv_bfloat16 g_wout[C_ * C_];
__device__ __nv_bfloat16 g_q [B_ * NH * N_ * DH];
__device__ __nv_bfloat16 g_k [B_ * NH * N_ * DH];
__device__ __nv_bfloat16 g_v [B_ * NH * N_ * DH];

// ---------------------------------------------------------------------------
// Helpers
// ---------------------------------------------------------------------------
__device__ __forceinline__ unsigned pack_bf16(float lo, float hi) {
    unsigned r;
    asm("cvt.rn.bf16x2.f32 %0, %1, %2;" : "=r"(r) : "f"(hi), "f"(lo));
    return r;
}
__device__ __forceinline__ float ex2f(float x) {
    float y;
    asm("ex2.approx.f32 %0, %1;" : "=f"(y) : "f"(x));
    return y;
}

__device__ __forceinline__ void mma16816(float* d, const unsigned* a,
                                         unsigned b0, unsigned b1) {
    asm volatile(
        "mma.sync.aligned.m16n8k16.row.col.f32.bf16.bf16.f32 "
        "{%0,%1,%2,%3}, {%4,%5,%6,%7}, {%8,%9}, {%0,%1,%2,%3};"
        : "+f"(d[0]), "+f"(d[1]), "+f"(d[2]), "+f"(d[3])
        : "r"(a[0]), "r"(a[1]), "r"(a[2]), "r"(a[3]), "r"(b0), "r"(b1));
}

__device__ __forceinline__ void ldsm_x4(unsigned* r, unsigned addr) {
    asm volatile("ldmatrix.sync.aligned.m8n8.x4.shared.b16 {%0,%1,%2,%3}, [%4];"
                 : "=r"(r[0]), "=r"(r[1]), "=r"(r[2]), "=r"(r[3]) : "r"(addr));
}
__device__ __forceinline__ void ldsm_x4_t(unsigned* r, unsigned addr) {
    asm volatile("ldmatrix.sync.aligned.m8n8.x4.trans.shared.b16 {%0,%1,%2,%3}, [%4];"
                 : "=r"(r[0]), "=r"(r[1]), "=r"(r[2]), "=r"(r[3]) : "r"(addr));
}

__device__ __forceinline__ void cp16(unsigned dst, const void* src, bool pred) {
    unsigned sz = pred ? 16u : 0u;
    asm volatile("cp.async.cg.shared.global [%0], [%1], 16, %2;"
                 :: "r"(dst), "l"(src), "r"(sz));
}
__device__ __forceinline__ void cp_commit() {
    asm volatile("cp.async.commit_group;" ::: "memory");
}
__device__ __forceinline__ void cp_wait1() {
    asm volatile("cp.async.wait_group 1;" ::: "memory");
}
__device__ __forceinline__ void cp_wait0() {
    asm volatile("cp.async.wait_group 0;" ::: "memory");
}

// Lane address for a 16x16 bf16 block at (row0, halfcol0); row stride 144B.
__device__ __forceinline__ unsigned frag_addr(unsigned base, int row0,
                                              int halfcol0, int lane) {
    int lrow = lane & 7, lm = lane >> 3;
    return base + (unsigned)((row0 + (lm & 1) * 8 + lrow) * 144 +
                             halfcol0 * 2 + (lm >> 1) * 16);
}

// ---------------------------------------------------------------------------
// Kernel 0: fp32 -> bf16 conversion of both weight matrices in one launch.
// ---------------------------------------------------------------------------
constexpr int CVT_NQ = 3 * C_ * C_ / 2;
constexpr int CVT_NO = C_ * C_ / 2;
__global__ void cvt_kernel(const float* __restrict__ qkvw,
                           const float* __restrict__ outw) {
    int i = blockIdx.x * blockDim.x + threadIdx.x;
    if (i < CVT_NQ) {
        float2 v = *(const float2*)(qkvw + (size_t)i * 2);
        ((unsigned*)g_wqkv)[i] = pack_bf16(v.x, v.y);
    } else if (i < CVT_NQ + CVT_NO) {
        int j = i - CVT_NQ;
        float2 v = *(const float2*)(outw + (size_t)j * 2);
        ((unsigned*)g_wout)[j] = pack_bf16(v.x, v.y);
    }
}

// ---------------------------------------------------------------------------
// Kernel 1: LayerNorm, coalesced two-pass.
// ---------------------------------------------------------------------------
__global__ void __launch_bounds__(256) ln_kernel(
        const float* __restrict__ x,
        const float* __restrict__ w,
        const float* __restrict__ bnorm) {
    __shared__ float s1s[8][32], s2s[8][32];
    __shared__ float smu[32], sinv[32];
    __shared__ float tile[32][66];

    int tid = threadIdx.x, wrp = tid >> 5, lane = tid & 31;
    int m  = blockIdx.x * 32 + lane;
    int mc = m < M_ ? m : M_ - 1;
    int b = mc / N_, n = mc % N_;
    const float* xb = x + (size_t)b * C_ * N_ + n;

    float s1 = 0.f, s2 = 0.f;
    for (int c = wrp; c < C_; c += 8) {
        float v = xb[(size_t)c * N_];
        s1 += v; s2 += v * v;
    }
    s1s[wrp][lane] = s1; s2s[wrp][lane] = s2;
    __syncthreads();
    if (wrp == 0) {
        float a = 0.f, q = 0.f;
        #pragma unroll
        for (int i = 0; i < 8; ++i) { a += s1s[i][lane]; q += s2s[i][lane]; }
        float mu = a * (1.f / C_);
        float var = q * (1.f / C_) - mu * mu;
        smu[lane] = mu;
        sinv[lane] = rsqrtf(var + 1e-5f);
    }
    __syncthreads();
    float mu = smu[lane], inv = sinv[lane];

    for (int ch = 0; ch < C_ / 64; ++ch) {
        #pragma unroll
        for (int j = 0; j < 8; ++j) {
            int cl = wrp + 8 * j;
            int c = ch * 64 + cl;
            float v = xb[(size_t)c * N_];
            tile[lane][cl] = (v - mu) * inv * w[c] + bnorm[c];
        }
        __syncthreads();
        #pragma unroll
        for (int r = 0; r < 4; ++r) {
            int idx = tid + r * 256;
            int tok = idx >> 5, chalf = idx & 31;
            int mm = blockIdx.x * 32 + tok;
            if (mm < M_) {
                float lo = tile[tok][chalf * 2];
                float hi = tile[tok][chalf * 2 + 1];
                ((unsigned*)g_tn)[((size_t)mm * C_ + ch * 64) / 2 + chalf] =
                    pack_bf16(lo, hi);
            }
        }
        __syncthreads();
    }
}

// ---------------------------------------------------------------------------
// Kernel 2: QKV GEMM, 128x128 tile, cp.async double-buffered.
// Q output pre-scaled by QSCALE.
// ---------------------------------------------------------------------------
constexpr unsigned QKV_BUF = 36864u;
constexpr unsigned QKV_SMEM = 2 * QKV_BUF;

__global__ void __launch_bounds__(256) qkv_mma_kernel() {
    extern __shared__ __align__(16) char dsm[];
    unsigned smb = (unsigned)__cvta_generic_to_shared(dsm);

    int m0 = blockIdx.y * 128;
    int j0 = blockIdx.x * 128;
    int tid = threadIdx.x;
    int w = tid >> 5, lane = tid & 31;
    int wm = (w & 3) * 32;
    int wn = (w >> 2) * 64;
    int gr = lane >> 2, qd = lane & 3;

    auto stage = [&](int buf, int k0) {
        unsigned ab = smb + buf * QKV_BUF;
        unsigned bb = ab + 18432u;
        #pragma unroll
        for (int r = 0; r < 4; ++r) {
            int idx = tid + r * 256;
            int row = idx >> 3, seg = idx & 7;
            int m = m0 + row;
            cp16(ab + row * 144 + seg * 16,
                 g_tn + (size_t)m * C_ + k0 + seg * 8, m < M_);
            cp16(bb + row * 144 + seg * 16,
                 g_wqkv + (size_t)(j0 + row) * C_ + k0 + seg * 8, true);
        }
        cp_commit();
    };

    float of[2][8][4] = {};
    constexpr int NC = C_ / 64;

    stage(0, 0);
    for (int kc = 0; kc < NC; ++kc) {
        if (kc + 1 < NC) { stage((kc + 1) & 1, (kc + 1) * 64); cp_wait1(); }
        else             { cp_wait0(); }
        __syncthreads();

        unsigned ab = smb + (kc & 1) * QKV_BUF;
        unsigned bb = ab + 18432u;
        #pragma unroll
        for (int ks = 0; ks < 4; ++ks) {
            unsigned a0[4], a1[4];
            ldsm_x4(a0, frag_addr(ab, wm,      ks * 16, lane));
            ldsm_x4(a1, frag_addr(ab, wm + 16, ks * 16, lane));
            #pragma unroll
            for (int nt = 0; nt < 4; ++nt) {
                unsigned b[4];
                ldsm_x4(b, frag_addr(bb, wn + nt * 16, ks * 16, lane));
                mma16816(of[0][nt * 2    ], a0, b[0], b[2]);
                mma16816(of[0][nt * 2 + 1], a0, b[1], b[3]);
                mma16816(of[1][nt * 2    ], a1, b[0], b[2]);
                mma16816(of[1][nt * 2 + 1], a1, b[1], b[3]);
            }
        }
        __syncthreads();
    }

    int js = j0 + wn;
    int s = js / C_;
    int h = (js % C_) / DH;
    __nv_bfloat16* outp = (s == 0) ? g_q : ((s == 1) ? g_k : g_v);
    float sc = (s == 0) ? QSCALE : 1.0f;
    unsigned* o32 = (unsigned*)outp;
    #pragma unroll
    for (int mt = 0; mt < 2; ++mt) {
        int ma = m0 + wm + mt * 16 + gr;
        int mb2 = ma + 8;
        #pragma unroll
        for (int j = 0; j < 8; ++j) {
            int e = j * 8 + qd * 2;
            if (ma < M_) {
                int b = ma / N_, n = ma % N_;
                o32[((size_t)((b * NH + h) * N_ + n) * DH + e) >> 1] =
                    pack_bf16(of[mt][j][0] * sc, of[mt][j][1] * sc);
            }
            if (mb2 < M_) {
                int b = mb2 / N_, n = mb2 % N_;
                o32[((size_t)((b * NH + h) * N_ + n) * DH + e) >> 1] =
                    pack_bf16(of[mt][j][2] * sc, of[mt][j][3] * sc);
            }
        }
    }
}

// ---------------------------------------------------------------------------
// Kernel 3: attention — round-15 compute shape (128 queries, 256 threads,
// regs ~80) with a 2-stage K/V ring (trailing barrier per tile, protocol
// proven in qkv) so smem = 55296B -> 4 CTAs/SM -> all 528 CTAs in ONE wave.
// Per-key-group fused loop identical to round 15.
// smem: Qs @0 (18432) + 2 x (K 9216 | V 9216) = 55296B.
// ---------------------------------------------------------------------------
constexpr unsigned ATT_RING  = 18432u;
constexpr unsigned ATT_STAGE = 18432u;
constexpr unsigned ATT_SMEM  = 18432u + 2 * ATT_STAGE;   // 55296

__global__ void __launch_bounds__(256, 4) attn_mma_kernel() {
    extern __shared__ __align__(16) char dsm[];
    unsigned smb = (unsigned)__cvta_generic_to_shared(dsm);

    int bh = blockIdx.x;
    int q0 = blockIdx.y * 128;
    const __nv_bfloat16* qb = g_q + (size_t)bh * N_ * DH;
    const __nv_bfloat16* kb = g_k + (size_t)bh * N_ * DH;
    const __nv_bfloat16* vb = g_v + (size_t)bh * N_ * DH;

    int tid  = threadIdx.x;
    int w    = tid >> 5, lane = tid & 31;
    int wq   = w * 16;
    int gr   = lane >> 2;
    int qd   = lane & 3;
    int row4 = tid >> 2, q4 = tid & 3;

    auto stage = [&](int buf, int kb0) {
        int n = kb0 + row4;
        bool ok = n < N_;
        unsigned base = smb + ATT_RING + buf * ATT_STAGE;
        unsigned kdst = base + row4 * 144 + q4 * 32;
        unsigned vdst = base + 9216u + row4 * 144 + q4 * 32;
        const char* ksrc = (const char*)(kb + (size_t)n * DH + q4 * 16);
        const char* vsrc = (const char*)(vb + (size_t)n * DH + q4 * 16);
        cp16(kdst,      ksrc,      ok);
        cp16(kdst + 16, ksrc + 16, ok);
        cp16(vdst,      vsrc,      ok);
        cp16(vdst + 16, vsrc + 16, ok);
        cp_commit();
    };

    {   // stage Q tile: 128 rows x 64 bf16
        #pragma unroll
        for (int r = 0; r < 4; ++r) {
            int idx = tid + r * 256;
            int row = idx >> 3, seg = idx & 7;
            int n = q0 + row;
            uint4 v = make_uint4(0u,0u,0u,0u);
            if (n < N_)
                v = *(const uint4*)(qb + (size_t)n * DH + seg * 8);
            *(uint4*)((unsigned*)dsm + row * 36 + seg * 4) = v;
        }
    }

    constexpr int NT = (N_ + 63) / 64;
    stage(0, 0);
    __syncthreads();

    unsigned qa[4][4];
    #pragma unroll
    for (int ks = 0; ks < 4; ++ks)
        ldsm_x4(qa[ks], frag_addr(smb, wq, ks * 16, lane));

    float of[8][4] = {};
    float lp0 = 0.f, lp1 = 0.f;

    for (int kc = 0; kc < NT; ++kc) {
        int kb0 = kc * 64;
        if (kc + 1 < NT) { stage((kc + 1) & 1, kb0 + 64); cp_wait1(); }
        else             { cp_wait0(); }
        __syncthreads();                     // buffer kc&1 visible

        unsigned ksb = smb + ATT_RING + (kc & 1) * ATT_STAGE;
        unsigned vsb = ksb + 9216u;
        bool full = (kb0 + 64 <= N_);

        #pragma unroll
        for (int p = 0; p < 4; ++p) {        // 16-key group
            float s0[4] = {}, s1[4] = {};
            #pragma unroll
            for (int ks = 0; ks < 4; ++ks) {
                unsigned bb[4];
                ldsm_x4(bb, frag_addr(ksb, p * 16, ks * 16, lane));
                mma16816(s0, qa[ks], bb[0], bb[2]);
                mma16816(s1, qa[ks], bb[1], bb[3]);
            }

            unsigned a[4];
            if (full) {
                float p0 = ex2f(s0[0]), p1 = ex2f(s0[1]);
                float p2 = ex2f(s0[2]), p3 = ex2f(s0[3]);
                float p4 = ex2f(s1[0]), p5 = ex2f(s1[1]);
                float p6 = ex2f(s1[2]), p7 = ex2f(s1[3]);
                lp0 += (p0 + p1) + (p4 + p5);
                lp1 += (p2 + p3) + (p6 + p7);
                a[0] = pack_bf16(p0, p1); a[1] = pack_bf16(p2, p3);
                a[2] = pack_bf16(p4, p5); a[3] = pack_bf16(p6, p7);
            } else {
                int gk0 = kb0 + p * 16 + qd * 2;
                int gk1 = gk0 + 8;
                bool u0 = gk0 < N_, u1 = (gk0 + 1) < N_;
                bool u2 = gk1 < N_, u3 = (gk1 + 1) < N_;
                float p0 = u0 ? ex2f(s0[0]) : 0.f;
                float p1 = u1 ? ex2f(s0[1]) : 0.f;
                float p2 = u0 ? ex2f(s0[2]) : 0.f;
                float p3 = u1 ? ex2f(s0[3]) : 0.f;
                float p4 = u2 ? ex2f(s1[0]) : 0.f;
                float p5 = u3 ? ex2f(s1[1]) : 0.f;
                float p6 = u2 ? ex2f(s1[2]) : 0.f;
                float p7 = u3 ? ex2f(s1[3]) : 0.f;
                lp0 += (p0 + p1) + (p4 + p5);
                lp1 += (p2 + p3) + (p6 + p7);
                a[0] = pack_bf16(p0, p1); a[1] = pack_bf16(p2, p3);
                a[2] = pack_bf16(p4, p5); a[3] = pack_bf16(p6, p7);
            }

            #pragma unroll
            for (int g = 0; g < 4; ++g) {
                unsigned v[4];
                ldsm_x4_t(v, frag_addr(vsb, p * 16, g * 16, lane));
                mma16816(of[2 * g    ], a, v[0], v[1]);
                mma16816(of[2 * g + 1], a, v[2], v[3]);
            }
        }
        __syncthreads();                     // frag reads done; buffer reusable
    }

    lp0 += __shfl_xor_sync(0xffffffffu, lp0, 1);
    lp0 += __shfl_xor_sync(0xffffffffu, lp0, 2);
    lp1 += __shfl_xor_sync(0xffffffffu, lp1, 1);
    lp1 += __shfl_xor_sync(0xffffffffu, lp1, 2);
    float invl0 = 1.f / lp0;
    float invl1 = 1.f / lp1;

    int b = bh / NH, h = bh % NH;
    int n0 = q0 + wq + gr;
    int n1 = n0 + 8;
    unsigned* ao32 = reinterpret_cast<unsigned*>(g_ao);
    #pragma unroll
    for (int t = 0; t < 8; ++t) {
        int e = t * 8 + qd * 2;
        if (n0 < N_)
            ao32[((size_t)(b * N_ + n0) * C_ + h * DH + e) >> 1] =
                pack_bf16(of[t][0] * invl0, of[t][1] * invl0);
        if (n1 < N_)
            ao32[((size_t)(b * N_ + n1) * C_ + h * DH + e) >> 1] =
                pack_bf16(of[t][2] * invl1, of[t][3] * invl1);
    }
}

// ---------------------------------------------------------------------------
// Kernel 4: out projection, 128x64 tile, cp.async double-buffered.
// ---------------------------------------------------------------------------
constexpr unsigned PROJ_BUF  = 27648u;
constexpr unsigned PROJ_SMEM = 2 * PROJ_BUF;

__global__ void __launch_bounds__(256) proj_mma_kernel(
        const float* __restrict__ bout,
        const float* __restrict__ x,
        float* __restrict__ out) {
    extern __shared__ __align__(16) char dsm[];
    unsigned smb = (unsigned)__cvta_generic_to_shared(dsm);
    float* Ts = (float*)dsm;

    int m0 = blockIdx.y * 128;
    int c0 = blockIdx.x * 64;
    int tid = threadIdx.x;
    int w = tid >> 5, lane = tid & 31;
    int wm = (w & 3) * 32;
    int wn = (w >> 2) * 32;
    int gr = lane >> 2, qd = lane & 3;

    auto stage = [&](int buf, int k0) {
        unsigned ab = smb + buf * PROJ_BUF;
        unsigned bb = ab + 18432u;
        #pragma unroll
        for (int r = 0; r < 4; ++r) {
            int idx = tid + r * 256;
            int row = idx >> 3, seg = idx & 7;
            int m = m0 + row;
            cp16(ab + row * 144 + seg * 16,
                 g_ao + (size_t)m * C_ + k0 + seg * 8, m < M_);
        }
        #pragma unroll
        for (int r = 0; r < 2; ++r) {
            int idx = tid + r * 256;
            int row = idx >> 3, seg = idx & 7;
            cp16(bb + row * 144 + seg * 16,
                 g_wout + (size_t)(c0 + row) * C_ + k0 + seg * 8, true);
        }
        cp_commit();
    };

    float of[2][4][4] = {};
    constexpr int NC = C_ / 64;

    stage(0, 0);
    for (int kc = 0; kc < NC; ++kc) {
        if (kc + 1 < NC) { stage((kc + 1) & 1, (kc + 1) * 64); cp_wait1(); }
        else             { cp_wait0(); }
        __syncthreads();

        unsigned ab = smb + (kc & 1) * PROJ_BUF;
        unsigned bb = ab + 18432u;
        #pragma unroll
        for (int ks = 0; ks < 4; ++ks) {
            unsigned a0[4], a1[4];
            ldsm_x4(a0, frag_addr(ab, wm,      ks * 16, lane));
            ldsm_x4(a1, frag_addr(ab, wm + 16, ks * 16, lane));
            #pragma unroll
            for (int nt = 0; nt < 2; ++nt) {
                unsigned b[4];
                ldsm_x4(b, frag_addr(bb, wn + nt * 16, ks * 16, lane));
                mma16816(of[0][nt * 2    ], a0, b[0], b[2]);
                mma16816(of[0][nt * 2 + 1], a0, b[1], b[3]);
                mma16816(of[1][nt * 2    ], a1, b[0], b[2]);
                mma16816(of[1][nt * 2 + 1], a1, b[1], b[3]);
            }
        }
        __syncthreads();
    }

    #pragma unroll
    for (int mt = 0; mt < 2; ++mt) {
        #pragma unroll
        for (int j = 0; j < 4; ++j) {
            int cl = wn + j * 8 + qd * 2;
            float b0 = bout[c0 + cl], b1 = bout[c0 + cl + 1];
            int r0 = wm + mt * 16 + gr;
            Ts[r0 * 65 + cl]           = of[mt][j][0] + b0;
            Ts[r0 * 65 + cl + 1]       = of[mt][j][1] + b1;
            Ts[(r0 + 8) * 65 + cl]     = of[mt][j][2] + b0;
            Ts[(r0 + 8) * 65 + cl + 1] = of[mt][j][3] + b1;
        }
    }
    __syncthreads();

    for (int t = tid; t < 128 * 64; t += 256) {
        int cl = t >> 7, ml = t & 127;
        int m = m0 + ml;
        if (m < M_) {
            int b = m / N_, n = m % N_;
            size_t gi = (size_t)(b * C_ + c0 + cl) * N_ + n;
            out[gi] = Ts[ml * 65 + cl] + x[gi];
        }
    }
}

// ---------------------------------------------------------------------------
extern "C" void kernel_launch(void* const* d_in, const int* in_sizes, int n_in,
                              void* d_out, int out_size) {
    const float* x      = nullptr;
    const float* norm_w = nullptr;
    const float* norm_b = nullptr;
    const float* qkv_w  = nullptr;
    const float* out_w  = nullptr;
    const float* out_b  = nullptr;
    int small_seen = 0;
    for (int i = 0; i < n_in; ++i) {
        const float* p = (const float*)d_in[i];
        int sz = in_sizes[i];
        if      (sz == B_ * C_ * N_)     x     = p;
        else if (sz == 3 * C_ * C_)      qkv_w = p;
        else if (sz == C_ * C_)          out_w = p;
        else if (sz == C_) {
            if      (small_seen == 0) norm_w = p;
            else if (small_seen == 1) norm_b = p;
            else                      out_b  = p;
            ++small_seen;
        }
    }
    float* out = (float*)d_out;
    (void)out_size;

    // Idempotent, host-side, capture-safe.
    cudaFuncSetAttribute(qkv_mma_kernel,
                         cudaFuncAttributeMaxDynamicSharedMemorySize, QKV_SMEM);
    cudaFuncSetAttribute(attn_mma_kernel,
                         cudaFuncAttributeMaxDynamicSharedMemorySize, ATT_SMEM);
    cudaFuncSetAttribute(proj_mma_kernel,
                         cudaFuncAttributeMaxDynamicSharedMemorySize, PROJ_SMEM);

    cvt_kernel<<<(CVT_NQ + CVT_NO + 255) / 256, 256>>>(qkv_w, out_w);
    ln_kernel<<<(M_ + 31) / 32, 256>>>(x, norm_w, norm_b);
    qkv_mma_kernel<<<dim3(3 * C_ / 128, (M_ + 127) / 128), 256, QKV_SMEM>>>();
    attn_mma_kernel<<<dim3(B_ * NH, (N_ + 127) / 128), 256, ATT_SMEM>>>();
    proj_mma_kernel<<<dim3(C_ / 64, (M_ + 127) / 128), 256, PROJ_SMEM>>>(out_b, x, out);
}